// round 17
// baseline (speedup 1.0000x reference)
#include <cuda_runtime.h>
#include <cuda_bf16.h>
#include <stdint.h>

// Problem constants (TokenSelector: B=32, D=256, H=W=64)
#define BB 32
#define DD 256
#define NN 4096          // H*W
#define KK 2048          // NN * KEEP_RATIO

// ---------------- scratch (device globals; no allocation allowed) ----------
__device__ unsigned g_keys[BB * NN];   // monotone-sortable score keys
__device__ int      g_pos [BB * NN];   // output row per token, -1 if dropped
__device__ int      g_flag[BB];        // per-batch "pos ready" flags

// float -> monotone-increasing uint key
__device__ __forceinline__ unsigned f2k(float f) {
    unsigned u = __float_as_uint(f);
    return u ^ ((u >> 31) ? 0xFFFFFFFFu : 0x80000000u);
}

// ---------------------------------------------------------------------------
// Kernel 1: per-token ordering key.  score = rstd*(dot(x,w') - mu*sum(w'))
// (softmax / norm_b / fc_b are order-irrelevant).
// Thread owns a QUAD of 4 consecutive tokens over a 64-wide d-slice
// (4 splits). Warp = one d-slice x 32 quads -> 512B contiguous per LDG.128.
// grid (16, 32) = 512 blocks, block 256 -> single resident wave.
// (Exact R5 config: measured 24.4-25us @ 5.6TB/s read ceiling.)
// ---------------------------------------------------------------------------
__global__ void __launch_bounds__(256)
score_kernel(const float* __restrict__ tokens,
             const float* __restrict__ norm_w,
             const float* __restrict__ fc_w,
             unsigned*    __restrict__ keys)
{
    __shared__ float  wsh[DD];
    __shared__ float4 r1[4][64], r2[4][64], r3[4][64];
    __shared__ float  rw[4][64];

    const int tid   = threadIdx.x;
    const int q     = tid & 63;     // token-quad slot within block (0..63)
    const int split = tid >> 6;     // d-slice 0..3 (64 d's each)

    wsh[tid] = norm_w[tid] * fc_w[tid];
    __syncthreads();

    const unsigned b  = blockIdx.y;
    const unsigned n4 = blockIdx.x * 64u + (unsigned)q;   // quad index 0..1023
    const float4* p = (const float4*)tokens + (b * (DD * (NN / 4)) + n4);

    float4 s1 = {0.f,0.f,0.f,0.f}, s2 = s1, sd = s1;
    float  sw = 0.f;
#pragma unroll
    for (int j0 = 0; j0 < 64; j0 += 4) {
        float4 x[4];
#pragma unroll
        for (int jj = 0; jj < 4; ++jj)             // 4 independent 16B LDGs
            x[jj] = p[(unsigned)(split * 64 + j0 + jj) * (NN / 4u)];
#pragma unroll
        for (int jj = 0; jj < 4; ++jj) {
            float w = wsh[split * 64 + j0 + jj];
            s1.x += x[jj].x;           s1.y += x[jj].y;
            s1.z += x[jj].z;           s1.w += x[jj].w;
            s2.x += x[jj].x * x[jj].x; s2.y += x[jj].y * x[jj].y;
            s2.z += x[jj].z * x[jj].z; s2.w += x[jj].w * x[jj].w;
            sd.x += x[jj].x * w;       sd.y += x[jj].y * w;
            sd.z += x[jj].z * w;       sd.w += x[jj].w * w;
            sw   += w;
        }
    }
    if (split != 0) {
        r1[split][q] = s1; r2[split][q] = s2; r3[split][q] = sd; rw[split][q] = sw;
    }
    __syncthreads();

    if (split == 0) {                               // 2 warps finalize 64 quads
#pragma unroll
        for (int s = 1; s < 4; ++s) {
            float4 a = r1[s][q], c = r2[s][q], d = r3[s][q];
            s1.x += a.x; s1.y += a.y; s1.z += a.z; s1.w += a.w;
            s2.x += c.x; s2.y += c.y; s2.z += c.z; s2.w += c.w;
            sd.x += d.x; sd.y += d.y; sd.z += d.z; sd.w += d.w;
            sw   += rw[s][q];
        }
        const float inv = 1.0f / (float)DD;
        uint4 kv;
        float mu, var;
        mu = s1.x*inv; var = fmaxf(s2.x*inv - mu*mu, 0.f);
        kv.x = f2k((sd.x - mu*sw) * rsqrtf(var + 1e-5f));
        mu = s1.y*inv; var = fmaxf(s2.y*inv - mu*mu, 0.f);
        kv.y = f2k((sd.y - mu*sw) * rsqrtf(var + 1e-5f));
        mu = s1.z*inv; var = fmaxf(s2.z*inv - mu*mu, 0.f);
        kv.z = f2k((sd.z - mu*sw) * rsqrtf(var + 1e-5f));
        mu = s1.w*inv; var = fmaxf(s2.w*inv - mu*mu, 0.f);
        kv.w = f2k((sd.w - mu*sw) * rsqrtf(var + 1e-5f));
        ((uint4*)keys)[b * (NN / 4u) + n4] = kv;
    }
}

// ============================================================================
// Select role (256 threads, 16 keys/thread): radix-select KK-th largest +
// rank compaction. Warp-aggregated histogram atomics, parallel suffix-scan
// bin pick, packed shuffle-scan compaction. lax.top_k tie rules (lowest
// indices win at threshold). Correctness-validated in R10/R14.
// ============================================================================
__device__ void select_role(const unsigned* __restrict__ keys,
                            int* __restrict__ pos, int b, char* sm)
{
    int*      hist     = (int*)sm;            // 1KB
    int*      wsum     = (int*)(sm + 1024);   // 32B
    unsigned* s_prefix = (unsigned*)(sm + 1056);
    int*      s_R      = (int*)(sm + 1060);

    const int tid  = threadIdx.x;
    const int lane = tid & 31;
    const int wid  = tid >> 5;

    unsigned k[16];
#pragma unroll
    for (int i = 0; i < 4; ++i) {
        uint4 kv = ((const uint4*)(keys + b * NN))[tid * 4 + i];
        k[i*4+0] = kv.x; k[i*4+1] = kv.y; k[i*4+2] = kv.z; k[i*4+3] = kv.w;
    }
    if (tid == 0) { *s_prefix = 0u; *s_R = KK; }
    __syncthreads();

    unsigned mask = 0u;
    for (int shift = 24; shift >= 0; shift -= 8) {
        hist[tid] = 0;
        __syncthreads();
        const unsigned prefix = *s_prefix;
        const int      R      = *s_R;

#pragma unroll
        for (int j = 0; j < 16; ++j) {
            int bin = ((k[j] & mask) == prefix) ? (int)((k[j] >> shift) & 255u) : 256;
            unsigned mm  = __match_any_sync(0xFFFFFFFFu, bin);
            int      ldr = __ffs(mm) - 1;
            if (lane == ldr && bin < 256)
                atomicAdd(&hist[bin], __popc(mm));
        }
        __syncthreads();

        int c = hist[255 - tid];
        int v = c;
#pragma unroll
        for (int o = 1; o < 32; o <<= 1) {
            int t = __shfl_up_sync(0xFFFFFFFFu, v, o);
            if (lane >= o) v += t;
        }
        if (lane == 31) wsum[wid] = v;
        __syncthreads();
        int S = v;
#pragma unroll
        for (int w = 0; w < 7; ++w)
            if (w < wid) S += wsum[w];
        if (S >= R && S - c < R) {                 // unique boundary thread
            *s_prefix = prefix | ((unsigned)(255 - tid) << shift);
            *s_R      = R - (S - c);
        }
        mask |= 255u << shift;
        __syncthreads();
    }
    const unsigned T    = *s_prefix;
    const int      Rfin = *s_R;

    int cg = 0, ce = 0;
#pragma unroll
    for (int j = 0; j < 16; ++j) { cg += (k[j] > T); ce += (k[j] == T); }
    int myv = (cg << 16) | ce;
    int v = myv;
#pragma unroll
    for (int o = 1; o < 32; o <<= 1) {
        int t = __shfl_up_sync(0xFFFFFFFFu, v, o);
        if (lane >= o) v += t;
    }
    if (lane == 31) wsum[wid] = v;
    __syncthreads();
    if (wid == 0 && lane < 8) {
        int t = wsum[lane];
#pragma unroll
        for (int o = 1; o < 8; o <<= 1) {
            int u = __shfl_up_sync(0x000000FFu, t, o);
            if (lane >= o) t += u;
        }
        wsum[lane] = t;
    }
    __syncthreads();
    int pre = v - myv + (wid > 0 ? wsum[wid - 1] : 0);
    int g = pre >> 16;
    int e = pre & 0xFFFF;

    int vals[16];
#pragma unroll
    for (int j = 0; j < 16; ++j) {
        int kp = -1;
        if (k[j] > T)       { kp = g + min(e, Rfin); ++g; }
        else if (k[j] == T) { if (e < Rfin) kp = g + e; ++e; }
        vals[j] = kp;
    }
#pragma unroll
    for (int i = 0; i < 4; ++i) {
        int4 op = { vals[i*4+0], vals[i*4+1], vals[i*4+2], vals[i*4+3] };
        ((int4*)(pos + b * NN))[tid * 4 + i] = op;
    }
}

// ---------------------------------------------------------------------------
// Kernel 2: FUSED select + gather. Blocks 0..31 run select (keys are L2-hot
// from score). Blocks 32+ gather: PREFETCH the full 32-token x 256-d tile
// into smem FIRST (reads depend only on tokens), then wait on the per-batch
// flag (select finishes in ~4us, hidden behind the tile-load latency of the
// first gather wave), then write kept rows as contiguous 1KB lines (__stcs).
// Select blocks are lowest-indexed & dispatched first -> no deadlock.
// grid: 32 + 4096 blocks, block 256. smem ~34KB -> 4+ blocks/SM.
// ---------------------------------------------------------------------------
__global__ void __launch_bounds__(256)
selgather_kernel(const float* __restrict__ tokens,
                 const unsigned* __restrict__ keys,
                 int* __restrict__ pos,
                 float* __restrict__ out)
{
    __shared__ __align__(16) char sm[33920];

    const int tid = threadIdx.x;

    if (blockIdx.x < BB) {                        // ---- select role ----
        const int b = blockIdx.x;
        select_role(keys, pos, b, sm);
        __syncthreads();
        __threadfence();                          // release pos
        if (tid == 0) atomicExch(&g_flag[b], 1);
        return;
    }

    // ---- gather role: PREFETCH -> WAIT -> WRITE ----
    float (*tile)[33] = (float(*)[33])sm;         // 256 x 33 floats = 33792B
    int*   spos       = (int*)(sm + 33792);       // 128B (pre-scaled p*DD)

    const int idx = blockIdx.x - BB;
    const int b   = idx >> 7;                     // 128 gather blocks per batch
    const int n0  = (idx & 127) * 32;

    const int f  = tid & 7;                       // float4 slot (4 tokens)
    const int d0 = tid >> 3;                      // 0..31
    const float* base = tokens + (unsigned)(b * (DD * NN)) + (unsigned)(n0 + f * 4);

    // Prefetch full tile: 8 independent LDG.128 per thread (no dependency).
#pragma unroll
    for (int j = 0; j < 8; ++j) {
        int d = d0 + j * 32;
        float4 v = *(const float4*)(base + (unsigned)d * NN);
        tile[d][f * 4 + 0] = v.x;
        tile[d][f * 4 + 1] = v.y;
        tile[d][f * 4 + 2] = v.z;
        tile[d][f * 4 + 3] = v.w;
    }

    // Wait for select(b) — overlapped with the tile-load latency above.
    if (tid == 0)
        while (atomicAdd(&g_flag[b], 0) == 0) __nanosleep(32);
    __syncthreads();
    __threadfence();                              // acquire pos
    if (tid < 32) {
        int p = pos[b * NN + n0 + tid];
        spos[tid] = (p >= 0) ? p * DD : -1;       // pre-scaled
    }
    __syncthreads();

    float* ob = out + (unsigned)(b * (KK * DD)) + (unsigned)tid;
#pragma unroll 4
    for (int kk = 0; kk < 32; ++kk) {
        int po = spos[kk];
        if (po >= 0)
            __stcs(ob + (unsigned)po, tile[tid][kk]);
    }
}

// ---------------------------------------------------------------------------
extern "C" void kernel_launch(void* const* d_in, const int* in_sizes, int n_in,
                              void* d_out, int out_size)
{
    const float* tokens = (const float*)d_in[0];
    const float* norm_w = (const float*)d_in[1];
    // d_in[2] = norm_b (order-irrelevant constant shift)
    const float* fc_w   = (const float*)d_in[3];
    // d_in[4] = fc_b   (order-irrelevant constant shift)
    float* out = (float*)d_out;

    unsigned* keys;
    int* pos;
    int* flag;
    cudaGetSymbolAddress((void**)&keys, g_keys);
    cudaGetSymbolAddress((void**)&pos,  g_pos);
    cudaGetSymbolAddress((void**)&flag, g_flag);

    cudaMemsetAsync(flag, 0, BB * sizeof(int));   // reset per-batch flags
    score_kernel<<<dim3(NN / 256, BB), 256>>>(tokens, norm_w, fc_w, keys);
    selgather_kernel<<<BB + NN / 32 * BB, 256>>>(tokens, keys, pos, out);
}